// round 10
// baseline (speedup 1.0000x reference)
#include <cuda_runtime.h>
#include <float.h>
#include <math.h>

// Problem constants (fixed shapes from reference setup_inputs)
#define D_DIM   2048
#define SK      64       // sqrt_K
#define NEXPERT 4096     // SK*SK
#define TOPK    8
#define NMAX    8192

typedef unsigned long long ULL;

// Scratch for fused projection S = x @ [W1;W2]^T  -> [N, 128]
__device__ float g_S[NMAX * 2 * SK];

// ---------------------------------------------------------------------------
// packed f32x2 helpers (exact fp32)
// ---------------------------------------------------------------------------
__device__ __forceinline__ ULL pk2(float lo, float hi) {
    ULL r;
    asm("mov.b64 %0, {%1, %2};" : "=l"(r) : "f"(lo), "f"(hi));
    return r;
}
__device__ __forceinline__ void fma2(ULL& d, ULL a, ULL b) {
    asm("fma.rn.f32x2 %0, %1, %2, %0;" : "+l"(d) : "l"(a), "l"(b));
}

// ---------------------------------------------------------------------------
// Kernel A: SGEMM  S[N,128] = x[N,2048] @ concat(W1,W2)[128,2048]^T
// Load-balanced: CTA = 56 rows (8 warps x 7 rows), grid = 147 <= 152 SMs,
// single wave, every SMSP carries 2 warps with 14 fma2/kk (was 16).
// Per-(row,col) accumulation: FMA over k ascending — bit-identical numerics
// to the previously passing kernels.
// ---------------------------------------------------------------------------
#define BMR 56          // rows per CTA
#define BMP 64          // padded row slots in As (8 per warp, 8th unused)
#define BN  128
#define BK  16
#define NIT (D_DIM / BK)

__global__ __launch_bounds__(256) void pkr_gemm(
    const float* __restrict__ x,
    const float* __restrict__ W1,
    const float* __restrict__ W2)
{
    __shared__ float As[2][BK][BMP];   // 2 x 4 KB  (row slots padded)
    __shared__ float Bs[2][BK][BN];    // 2 x 8 KB

    const int tid  = threadIdx.x;
    const int w    = tid >> 5;
    const int lane = tid & 31;
    const int bm0  = blockIdx.x * BMR;

    // A loader: logical row a_r (0..55) -> smem slot (a_r/7)*8 + a_r%7
    const int a_r   = tid >> 2;                 // 0..63; active if <56
    const int akc   = (tid & 3) * 4;
    const bool a_on = (a_r < BMR);
    const int a_slot = (a_r / 7) * 8 + (a_r % 7);
    int a_grow = bm0 + a_r;
    if (a_grow > NMAX - 1) a_grow = NMAX - 1;   // clamp (last CTA remainder)
    const float* xp = x + (size_t)a_grow * D_DIM + akc;

    // B loader: col bc (0..63), k offset bkc in {0,4,8,12}; W1 and W2 halves
    const int bc  = tid & 63;
    const int bkc = (tid >> 6) * 4;
    const float* w1p = W1 + (size_t)bc * D_DIM + bkc;
    const float* w2p = W2 + (size_t)bc * D_DIM + bkc;

    ULL acc[7][2];
    #pragma unroll
    for (int i = 0; i < 7; i++) { acc[i][0] = 0ULL; acc[i][1] = 0ULL; }

    // stage 0 fill
    {
        if (a_on) {
            float4 a = *(const float4*)xp;
            As[0][akc + 0][a_slot] = a.x;  As[0][akc + 1][a_slot] = a.y;
            As[0][akc + 2][a_slot] = a.z;  As[0][akc + 3][a_slot] = a.w;
        }
        float4 b1 = *(const float4*)w1p;
        float4 b2 = *(const float4*)w2p;
        Bs[0][bkc + 0][bc] = b1.x; Bs[0][bkc + 1][bc] = b1.y;
        Bs[0][bkc + 2][bc] = b1.z; Bs[0][bkc + 3][bc] = b1.w;
        Bs[0][bkc + 0][bc + SK] = b2.x; Bs[0][bkc + 1][bc + SK] = b2.y;
        Bs[0][bkc + 2][bc + SK] = b2.z; Bs[0][bkc + 3][bc + SK] = b2.w;
    }
    __syncthreads();

    int p = 0;
    float4 a_pf, b1_pf, b2_pf;
    for (int it = 0; it < NIT; ++it) {
        const bool has_next = (it + 1) < NIT;
        if (has_next) {
            const int k0 = (it + 1) * BK;
            if (a_on) a_pf = *(const float4*)(xp + k0);
            b1_pf = *(const float4*)(w1p + k0);
            b2_pf = *(const float4*)(w2p + k0);
        }

        #pragma unroll
        for (int kk = 0; kk < BK; kk++) {
            float4 a01 = *(const float4*)&As[p][kk][w * 8];
            float4 a23 = *(const float4*)&As[p][kk][w * 8 + 4];  // .w unused
            ulonglong2 bb = *(const ulonglong2*)&Bs[p][kk][lane * 4];
            float av[7] = {a01.x, a01.y, a01.z, a01.w,
                           a23.x, a23.y, a23.z};
            #pragma unroll
            for (int i = 0; i < 7; i++) {
                ULL ad = pk2(av[i], av[i]);
                fma2(acc[i][0], ad, bb.x);
                fma2(acc[i][1], ad, bb.y);
            }
        }

        if (has_next) {
            const int q = p ^ 1;
            if (a_on) {
                As[q][akc + 0][a_slot] = a_pf.x;  As[q][akc + 1][a_slot] = a_pf.y;
                As[q][akc + 2][a_slot] = a_pf.z;  As[q][akc + 3][a_slot] = a_pf.w;
            }
            Bs[q][bkc + 0][bc] = b1_pf.x; Bs[q][bkc + 1][bc] = b1_pf.y;
            Bs[q][bkc + 2][bc] = b1_pf.z; Bs[q][bkc + 3][bc] = b1_pf.w;
            Bs[q][bkc + 0][bc + SK] = b2_pf.x; Bs[q][bkc + 1][bc + SK] = b2_pf.y;
            Bs[q][bkc + 2][bc + SK] = b2_pf.z; Bs[q][bkc + 3][bc + SK] = b2_pf.w;
            __syncthreads();
            p = q;
        }
    }

    #pragma unroll
    for (int i = 0; i < 7; i++) {
        const int row = bm0 + w * 7 + i;
        if (row < NMAX) {
            ulonglong2 v; v.x = acc[i][0]; v.y = acc[i][1];
            *(ulonglong2*)&g_S[(size_t)row * (2 * SK) + lane * 4] = v;
        }
    }
}

// ---------------------------------------------------------------------------
// Kernel B (R9 verbatim, measured 24.7us): one warp per row; score stream
// interleaved into the s1/s2 argmax rounds; stable tie-breaks everywhere.
// ---------------------------------------------------------------------------
__global__ __launch_bounds__(256) void pkr_topk(
    float* __restrict__ idx_out,
    float* __restrict__ probs_out,
    float* __restrict__ scores_out)
{
    __shared__ float sb[8][2 * SK];
    __shared__ float c1v[8][8], c2v[8][8];
    __shared__ int   c1i[8][8], c2i[8][8];

    const int w    = threadIdx.x >> 5;
    const int lane = threadIdx.x & 31;
    const size_t row = (size_t)blockIdx.x * 8 + w;

    *(float4*)&sb[w][lane * 4] =
        *(const float4*)&g_S[row * (2 * SK) + lane * 4];
    __syncwarp();

    float* __restrict__ srow =
        scores_out ? scores_out + row * NEXPERT : (float*)0;
    const int j = (lane & 15) * 4;
    const float4 s2q = *(const float4*)&sb[w][SK + j];
    const int ihalf = lane >> 4;

    float a0 = sb[w][lane],      a1 = sb[w][lane + 32];
    int   i0 = lane,             i1 = lane + 32;
    float b0 = sb[w][SK + lane], b1 = sb[w][SK + lane + 32];
    int   j0 = lane,             j1 = lane + 32;

    #pragma unroll
    for (int r = 0; r < TOPK; r++) {
        if (srow) {
            #pragma unroll
            for (int u = 0; u < 4; u++) {
                const int t = r * 4 + u;
                const int i = t * 2 + ihalf;
                const float s1 = sb[w][i];
                float4 v4;
                v4.x = s1 + s2q.x; v4.y = s1 + s2q.y;
                v4.z = s1 + s2q.z; v4.w = s1 + s2q.w;
                __stcs((float4*)&srow[i * SK + j], v4);
            }
        }
        {
            float v; int i;
            if (a0 > a1 || (a0 == a1 && i0 < i1)) { v = a0; i = i0; }
            else                                  { v = a1; i = i1; }
            #pragma unroll
            for (int off = 16; off; off >>= 1) {
                float ov = __shfl_xor_sync(0xffffffffu, v, off);
                int   oi = __shfl_xor_sync(0xffffffffu, i, off);
                if (ov > v || (ov == v && oi < i)) { v = ov; i = oi; }
            }
            if (lane == r) { c1v[w][r] = v; c1i[w][r] = i; }
            if (i == i0) { a0 = -FLT_MAX; i0 = 1 << 30; }
            if (i == i1) { a1 = -FLT_MAX; i1 = 1 << 30; }
        }
        {
            float u; int jj;
            if (b0 > b1 || (b0 == b1 && j0 < j1)) { u = b0; jj = j0; }
            else                                  { u = b1; jj = j1; }
            #pragma unroll
            for (int off = 16; off; off >>= 1) {
                float ou = __shfl_xor_sync(0xffffffffu, u, off);
                int   oj = __shfl_xor_sync(0xffffffffu, jj, off);
                if (ou > u || (ou == u && oj < jj)) { u = ou; jj = oj; }
            }
            if (lane == r) { c2v[w][r] = u; c2i[w][r] = jj; }
            if (jj == j0) { b0 = -FLT_MAX; j0 = 1 << 30; }
            if (jj == j1) { b1 = -FLT_MAX; j1 = 1 << 30; }
        }
    }
    __syncwarp();

    const int p0 = lane, p1 = lane + 32;
    float cv0 = c1v[w][p0 >> 3] + c2v[w][p0 & 7];
    int   ci0 = c1i[w][p0 >> 3] * SK + c2i[w][p0 & 7];
    float cv1 = c1v[w][p1 >> 3] + c2v[w][p1 & 7];
    int   ci1 = c1i[w][p1 >> 3] * SK + c2i[w][p1 & 7];

    float mv[TOPK];
    int   mi[TOPK];
    #pragma unroll
    for (int r = 0; r < TOPK; r++) {
        float v; int i;
        if (cv0 > cv1 || (cv0 == cv1 && ci0 < ci1)) { v = cv0; i = ci0; }
        else                                        { v = cv1; i = ci1; }
        #pragma unroll
        for (int off = 16; off; off >>= 1) {
            float ov = __shfl_xor_sync(0xffffffffu, v, off);
            int   oi = __shfl_xor_sync(0xffffffffu, i, off);
            if (ov > v || (ov == v && oi < i)) { v = ov; i = oi; }
        }
        mv[r] = v; mi[r] = i;
        if (i == ci0) { cv0 = -FLT_MAX; ci0 = 1 << 30; }
        if (i == ci1) { cv1 = -FLT_MAX; ci1 = 1 << 30; }
    }

    if (lane == 0) {
        float m = mv[0], sum = 0.f, e[TOPK];
        #pragma unroll
        for (int r = 0; r < TOPK; r++) { e[r] = expf(mv[r] - m); sum += e[r]; }
        float inv = 1.f / sum;
        #pragma unroll
        for (int r = 0; r < TOPK; r++) {
            if (idx_out)   idx_out[row * TOPK + r]   = (float)mi[r];
            if (probs_out) probs_out[row * TOPK + r] = e[r] * inv;
        }
    }
}

// ---------------------------------------------------------------------------
extern "C" void kernel_launch(void* const* d_in, const int* in_sizes, int n_in,
                              void* d_out, int out_size) {
    const float* x  = (const float*)d_in[0];
    const float* W1 = (const float*)d_in[1];
    const float* W2 = (const float*)d_in[2];
    (void)n_in;

    int N = in_sizes[0] / D_DIM;   // 8192
    float* out = (float*)d_out;

    float* idxp = 0;
    float* probp = 0;
    float* scorep = 0;
    long long full = (long long)N * (2 * TOPK + NEXPERT);
    if ((long long)out_size == full) {
        idxp   = out;
        probp  = out + (long long)N * TOPK;
        scorep = out + (long long)N * 2 * TOPK;
    } else if ((long long)out_size == (long long)N * NEXPERT) {
        scorep = out;
    } else if ((long long)out_size == (long long)N * 2 * TOPK) {
        idxp  = out;
        probp = out + (long long)N * TOPK;
    } else {
        idxp   = out;
        probp  = out + (long long)N * TOPK;
        scorep = out + (long long)N * 2 * TOPK;
    }

    const int grid = (N + BMR - 1) / BMR;   // 147
    pkr_gemm<<<grid, 256>>>(x, W1, W2);
    pkr_topk<<<N / 8, 256>>>(idxp, probp, scorep);
}

// round 11
// speedup vs baseline: 1.1945x; 1.1945x over previous
#include <cuda_runtime.h>
#include <float.h>
#include <math.h>

// Problem constants (fixed shapes from reference setup_inputs)
#define D_DIM   2048
#define SK      64       // sqrt_K
#define NEXPERT 4096     // SK*SK
#define TOPK    8
#define NMAX    8192

typedef unsigned long long ULL;

// ---------------------------------------------------------------------------
// packed f32x2 helpers (exact fp32)
// ---------------------------------------------------------------------------
__device__ __forceinline__ ULL pk2(float lo, float hi) {
    ULL r;
    asm("mov.b64 %0, {%1, %2};" : "=l"(r) : "f"(lo), "f"(hi));
    return r;
}
__device__ __forceinline__ void fma2(ULL& d, ULL a, ULL b) {
    asm("fma.rn.f32x2 %0, %1, %2, %0;" : "+l"(d) : "l"(a), "l"(b));
}

// ---------------------------------------------------------------------------
// Fused kernel: R2's SGEMM (inner loop untouched) + in-CTA epilogue doing
// score streaming + decomposed top-8 + softmax for the CTA's own 64 rows.
// Dynamic smem 32KB: [0,24KB) = As/Bs during k-loop; whole 32KB reused as
// the 64x128 stage afterwards (protected by __syncthreads).
// ---------------------------------------------------------------------------
#define BM 64
#define BN 128
#define BK 16
#define NIT (D_DIM / BK)
#define SMEM_BYTES (BM * BN * 4)   // 32768

__global__ __launch_bounds__(256) void pkr_fused(
    const float* __restrict__ x,
    const float* __restrict__ W1,
    const float* __restrict__ W2,
    float* __restrict__ idx_out,
    float* __restrict__ probs_out,
    float* __restrict__ scores_out)
{
    extern __shared__ float sm[];
    float (*As)[BK][BM] = (float (*)[BK][BM])(sm);          // 2 x 4 KB
    float (*Bs)[BK][BN] = (float (*)[BK][BN])(sm + 2048);   // 2 x 8 KB

    __shared__ float c1v[8][8], c2v[8][8];
    __shared__ int   c1i[8][8], c2i[8][8];

    const int tid  = threadIdx.x;
    const int w    = tid >> 5;
    const int lane = tid & 31;
    const int bm0  = blockIdx.x * BM;

    // A loader: row ar (0..63) coalesced along k; k offset akc in {0,4,8,12}
    const int ar  = tid >> 2;
    const int akc = (tid & 3) * 4;
    const float* xp = x + (size_t)(bm0 + ar) * D_DIM + akc;

    // B loader: col bc (0..63), k offset bkc in {0,4,8,12}
    const int bc  = tid & 63;
    const int bkc = (tid >> 6) * 4;
    const float* w1p = W1 + (size_t)bc * D_DIM + bkc;
    const float* w2p = W2 + (size_t)bc * D_DIM + bkc;

    ULL acc[8][2];
    #pragma unroll
    for (int i = 0; i < 8; i++) { acc[i][0] = 0ULL; acc[i][1] = 0ULL; }

    // stage 0 fill
    {
        float4 a  = *(const float4*)xp;
        float4 b1 = *(const float4*)w1p;
        float4 b2 = *(const float4*)w2p;
        As[0][akc + 0][ar] = a.x;  As[0][akc + 1][ar] = a.y;
        As[0][akc + 2][ar] = a.z;  As[0][akc + 3][ar] = a.w;
        Bs[0][bkc + 0][bc] = b1.x; Bs[0][bkc + 1][bc] = b1.y;
        Bs[0][bkc + 2][bc] = b1.z; Bs[0][bkc + 3][bc] = b1.w;
        Bs[0][bkc + 0][bc + SK] = b2.x; Bs[0][bkc + 1][bc + SK] = b2.y;
        Bs[0][bkc + 2][bc + SK] = b2.z; Bs[0][bkc + 3][bc + SK] = b2.w;
    }
    __syncthreads();

    int p = 0;
    float4 a_pf, b1_pf, b2_pf;
    for (int it = 0; it < NIT; ++it) {
        const bool has_next = (it + 1) < NIT;
        if (has_next) {
            const int k0 = (it + 1) * BK;
            a_pf  = *(const float4*)(xp  + k0);
            b1_pf = *(const float4*)(w1p + k0);
            b2_pf = *(const float4*)(w2p + k0);
        }

        #pragma unroll
        for (int kk = 0; kk < BK; kk++) {
            float4 a01 = *(const float4*)&As[p][kk][w * 8];
            float4 a23 = *(const float4*)&As[p][kk][w * 8 + 4];
            ulonglong2 bb = *(const ulonglong2*)&Bs[p][kk][lane * 4];
            float av[8] = {a01.x, a01.y, a01.z, a01.w,
                           a23.x, a23.y, a23.z, a23.w};
            #pragma unroll
            for (int i = 0; i < 8; i++) {
                ULL ad = pk2(av[i], av[i]);
                fma2(acc[i][0], ad, bb.x);
                fma2(acc[i][1], ad, bb.y);
            }
        }

        if (has_next) {
            const int q = p ^ 1;
            As[q][akc + 0][ar] = a_pf.x;  As[q][akc + 1][ar] = a_pf.y;
            As[q][akc + 2][ar] = a_pf.z;  As[q][akc + 3][ar] = a_pf.w;
            Bs[q][bkc + 0][bc] = b1_pf.x; Bs[q][bkc + 1][bc] = b1_pf.y;
            Bs[q][bkc + 2][bc] = b1_pf.z; Bs[q][bkc + 3][bc] = b1_pf.w;
            Bs[q][bkc + 0][bc + SK] = b2_pf.x; Bs[q][bkc + 1][bc + SK] = b2_pf.y;
            Bs[q][bkc + 2][bc + SK] = b2_pf.z; Bs[q][bkc + 3][bc + SK] = b2_pf.w;
            __syncthreads();
            p = q;
        }
    }

    // ==== epilogue: stage S in smem (replaces g_S round-trip) ====
    __syncthreads();                      // all warps done reading As/Bs
    float* stage = sm;                    // [64][128]
    #pragma unroll
    for (int i = 0; i < 8; i++) {
        ulonglong2 v; v.x = acc[i][0]; v.y = acc[i][1];
        *(ulonglong2*)&stage[(w * 8 + i) * BN + lane * 4] = v;
    }
    __syncwarp();   // warp reads only its own 8 rows below

    // ==== per-row stream + decomposed top-8 + softmax (R9-proven code) ====
    const int jq = (lane & 15) * 4;
    const int ihalf = lane >> 4;

    for (int r8 = 0; r8 < 8; r8++) {
        const float* sbrow = &stage[(w * 8 + r8) * BN];
        const size_t grow = (size_t)(bm0 + w * 8 + r8);

        float* __restrict__ srow =
            scores_out ? scores_out + grow * NEXPERT : (float*)0;
        const float4 s2q = *(const float4*)&sbrow[SK + jq];

        float a0 = sbrow[lane],      a1 = sbrow[lane + 32];
        int   i0 = lane,             i1 = lane + 32;
        float b0 = sbrow[SK + lane], b1 = sbrow[SK + lane + 32];
        int   j0 = lane,             j1 = lane + 32;

        #pragma unroll
        for (int r = 0; r < TOPK; r++) {
            // interleaved stream (4 iters per round)
            if (srow) {
                #pragma unroll
                for (int u = 0; u < 4; u++) {
                    const int t = r * 4 + u;
                    const int i = t * 2 + ihalf;
                    const float s1 = sbrow[i];
                    float4 v4;
                    v4.x = s1 + s2q.x; v4.y = s1 + s2q.y;
                    v4.z = s1 + s2q.z; v4.w = s1 + s2q.w;
                    __stcs((float4*)&srow[i * SK + jq], v4);
                }
            }
            // s1 round r
            {
                float v; int i;
                if (a0 > a1 || (a0 == a1 && i0 < i1)) { v = a0; i = i0; }
                else                                  { v = a1; i = i1; }
                #pragma unroll
                for (int off = 16; off; off >>= 1) {
                    float ov = __shfl_xor_sync(0xffffffffu, v, off);
                    int   oi = __shfl_xor_sync(0xffffffffu, i, off);
                    if (ov > v || (ov == v && oi < i)) { v = ov; i = oi; }
                }
                if (lane == r) { c1v[w][r] = v; c1i[w][r] = i; }
                if (i == i0) { a0 = -FLT_MAX; i0 = 1 << 30; }
                if (i == i1) { a1 = -FLT_MAX; i1 = 1 << 30; }
            }
            // s2 round r
            {
                float u; int jj;
                if (b0 > b1 || (b0 == b1 && j0 < j1)) { u = b0; jj = j0; }
                else                                  { u = b1; jj = j1; }
                #pragma unroll
                for (int off = 16; off; off >>= 1) {
                    float ou = __shfl_xor_sync(0xffffffffu, u, off);
                    int   oj = __shfl_xor_sync(0xffffffffu, jj, off);
                    if (ou > u || (ou == u && oj < jj)) { u = ou; jj = oj; }
                }
                if (lane == r) { c2v[w][r] = u; c2i[w][r] = jj; }
                if (jj == j0) { b0 = -FLT_MAX; j0 = 1 << 30; }
                if (jj == j1) { b1 = -FLT_MAX; j1 = 1 << 30; }
            }
        }
        __syncwarp();

        // top-8 of the 64 candidate pairs (2 per lane)
        const int p0 = lane, p1 = lane + 32;
        float cv0 = c1v[w][p0 >> 3] + c2v[w][p0 & 7];
        int   ci0 = c1i[w][p0 >> 3] * SK + c2i[w][p0 & 7];
        float cv1 = c1v[w][p1 >> 3] + c2v[w][p1 & 7];
        int   ci1 = c1i[w][p1 >> 3] * SK + c2i[w][p1 & 7];

        float mv[TOPK];
        int   mi[TOPK];
        #pragma unroll
        for (int r = 0; r < TOPK; r++) {
            float v; int i;
            if (cv0 > cv1 || (cv0 == cv1 && ci0 < ci1)) { v = cv0; i = ci0; }
            else                                        { v = cv1; i = ci1; }
            #pragma unroll
            for (int off = 16; off; off >>= 1) {
                float ov = __shfl_xor_sync(0xffffffffu, v, off);
                int   oi = __shfl_xor_sync(0xffffffffu, i, off);
                if (ov > v || (ov == v && oi < i)) { v = ov; i = oi; }
            }
            mv[r] = v; mi[r] = i;
            if (i == ci0) { cv0 = -FLT_MAX; ci0 = 1 << 30; }
            if (i == ci1) { cv1 = -FLT_MAX; ci1 = 1 << 30; }
        }

        if (lane == 0) {
            float m = mv[0], sum = 0.f, e[TOPK];
            #pragma unroll
            for (int r = 0; r < TOPK; r++) { e[r] = expf(mv[r] - m); sum += e[r]; }
            float inv = 1.f / sum;
            #pragma unroll
            for (int r = 0; r < TOPK; r++) {
                if (idx_out)   idx_out[grow * TOPK + r]   = (float)mi[r];
                if (probs_out) probs_out[grow * TOPK + r] = e[r] * inv;
            }
        }
        __syncwarp();
    }
}

// ---------------------------------------------------------------------------
extern "C" void kernel_launch(void* const* d_in, const int* in_sizes, int n_in,
                              void* d_out, int out_size) {
    const float* x  = (const float*)d_in[0];
    const float* W1 = (const float*)d_in[1];
    const float* W2 = (const float*)d_in[2];
    (void)n_in;

    int N = in_sizes[0] / D_DIM;   // 8192
    float* out = (float*)d_out;

    float* idxp = 0;
    float* probp = 0;
    float* scorep = 0;
    long long full = (long long)N * (2 * TOPK + NEXPERT);
    if ((long long)out_size == full) {
        idxp   = out;
        probp  = out + (long long)N * TOPK;
        scorep = out + (long long)N * 2 * TOPK;
    } else if ((long long)out_size == (long long)N * NEXPERT) {
        scorep = out;
    } else if ((long long)out_size == (long long)N * 2 * TOPK) {
        idxp  = out;
        probp = out + (long long)N * TOPK;
    } else {
        idxp   = out;
        probp  = out + (long long)N * TOPK;
        scorep = out + (long long)N * 2 * TOPK;
    }

    cudaFuncSetAttribute(pkr_fused,
                         cudaFuncAttributeMaxDynamicSharedMemorySize,
                         SMEM_BYTES);
    pkr_fused<<<N / BM, 256, SMEM_BYTES>>>(x, W1, W2, idxp, probp, scorep);
}